// round 11
// baseline (speedup 1.0000x reference)
#include <cuda_runtime.h>
#include <cuda_fp16.h>
#include <cstdint>

// ============================================================================
// PackedBitLinear: out = x @ W^T * scale   (abs-max row scaling cancels).
// sm_103 harness target rejects tcgen05 -> legacy mma.sync (HMMA) path.
//   kernel 1: x fp32 -> fp16 scratch (read 16x by GEMM)
//   kernel 2: GEMM 128x256x64 tiles, 3-stage cp.async ring,
//             W decoded 2-bit -> fp16 directly into smem B tile (exact),
//             mma.sync.m16n8k16 f32.f16.f16.f32, epilogue * scale.
// ============================================================================

#define TOKENS 8192
#define NF 4096
#define KF 4096
#define PACKED_IN 256            // int32 per W row

#define BM 128
#define BN 256
#define BK 64                    // halves of K per stage
#define KT (KF / BK)             // 64
#define STAGES 3
#define LDSH 72                  // padded row stride in halves (144B), LDSM conflict-free
#define A_STG_B (BM * LDSH * 2)  // 18432 B
#define B_STG_B (BN * LDSH * 2)  // 36864 B
#define STG_B   (A_STG_B + B_STG_B)          // 55296
#define SMEM_TOTAL (STAGES * STG_B)          // 165888

static __device__ __half g_XH[(size_t)TOKENS * KF];   // 64 MB fp16 activations

// ---------------------------------------------------------------------------
__global__ void __launch_bounds__(256) convert_x_kernel(const float* __restrict__ x) {
    size_t i = (size_t)blockIdx.x * blockDim.x + threadIdx.x;   // 8-elem chunk
    const float4* p = reinterpret_cast<const float4*>(x) + 2 * i;
    float4 a = p[0], b = p[1];
    __half2 h0 = __floats2half2_rn(a.x, a.y), h1 = __floats2half2_rn(a.z, a.w);
    __half2 h2 = __floats2half2_rn(b.x, b.y), h3 = __floats2half2_rn(b.z, b.w);
    uint4 u;
    u.x = *reinterpret_cast<uint32_t*>(&h0); u.y = *reinterpret_cast<uint32_t*>(&h1);
    u.z = *reinterpret_cast<uint32_t*>(&h2); u.w = *reinterpret_cast<uint32_t*>(&h3);
    reinterpret_cast<uint4*>(g_XH)[i] = u;
}

// ---------------------------------------------------------------------------
__device__ __forceinline__ void ldsm_x4(uint32_t (&r)[4], uint32_t addr) {
    asm volatile("ldmatrix.sync.aligned.m8n8.x4.shared.b16 {%0,%1,%2,%3}, [%4];\n"
                 : "=r"(r[0]), "=r"(r[1]), "=r"(r[2]), "=r"(r[3]) : "r"(addr));
}
__device__ __forceinline__ void mma16816(float (&c)[4], const uint32_t (&a)[4],
                                         uint32_t b0, uint32_t b1) {
    asm volatile(
        "mma.sync.aligned.m16n8k16.row.col.f32.f16.f16.f32 "
        "{%0,%1,%2,%3},{%4,%5,%6,%7},{%8,%9},{%0,%1,%2,%3};\n"
        : "+f"(c[0]), "+f"(c[1]), "+f"(c[2]), "+f"(c[3])
        : "r"(a[0]), "r"(a[1]), "r"(a[2]), "r"(a[3]), "r"(b0), "r"(b1));
}
#define CP_ASYNC16(dst, src) \
    asm volatile("cp.async.cg.shared.global [%0], [%1], 16;\n" :: "r"(dst), "l"(src))
#define CP_COMMIT() asm volatile("cp.async.commit_group;\n" ::: "memory")
#define CP_WAIT(n)  asm volatile("cp.async.wait_group %0;\n" :: "n"(n) : "memory")
#define STS128(a, r0, r1, r2, r3) \
    asm volatile("st.shared.v4.b32 [%0], {%1,%2,%3,%4};" \
                 :: "r"(a), "r"(r0), "r"(r1), "r"(r2), "r"(r3) : "memory")

// decode one int32 (16 ternary {0,1,2}) -> 16 exact fp16 {-1,0,1} -> 32B smem
// half bits 0x6400|v == 1024+v exactly; hsub2 with 1025 -> v-1, exact.
__device__ __forceinline__ void dec32(uint32_t addr, int v) {
    const uint32_t c1025 = 0x64016401u;
    uint32_t r[8];
#pragma unroll
    for (int j = 0; j < 8; j++) {
        uint32_t lo = ((uint32_t)v >> (4 * j)) & 3u;
        uint32_t hi = ((uint32_t)v >> (4 * j + 2)) & 3u;
        uint32_t pk = 0x64006400u | lo | (hi << 16);
        __half2 h = __hsub2(*reinterpret_cast<__half2*>(&pk),
                            *reinterpret_cast<const __half2*>(&c1025));
        r[j] = *reinterpret_cast<uint32_t*>(&h);
    }
    STS128(addr,      r[0], r[1], r[2], r[3]);
    STS128(addr + 16, r[4], r[5], r[6], r[7]);
}

// issue A cp.async + decode B for one stage
__device__ __forceinline__ void load_stage(char* smem, int slot, int kt,
                                           int bm0, int bn0, int tid,
                                           const int* __restrict__ pw) {
    char* stg = smem + slot * STG_B;
    // ---- A: 128 rows x 128B, 1024 x 16B chunks, 256 threads x 4 ----
    const __half* gk = g_XH + (size_t)bm0 * KF + (size_t)kt * BK;
    uint32_t sA = (uint32_t)__cvta_generic_to_shared(stg);
#pragma unroll
    for (int t = 0; t < 4; t++) {
        int c = tid + t * 256;
        int row = c >> 3, ci = c & 7;
        CP_ASYNC16(sA + (uint32_t)row * (LDSH * 2) + ci * 16,
                   gk + (size_t)row * KF + ci * 8);
    }
    // ---- B: one W row per thread, 4 ints -> 64 halves ----
    int4 p4 = __ldg(reinterpret_cast<const int4*>(
                        pw + (size_t)(bn0 + tid) * PACKED_IN + (size_t)kt * 4));
    uint32_t rb = (uint32_t)__cvta_generic_to_shared(stg + A_STG_B)
                + (uint32_t)tid * (LDSH * 2);
    dec32(rb,      p4.x);
    dec32(rb + 32, p4.y);
    dec32(rb + 64, p4.z);
    dec32(rb + 96, p4.w);
}

// ---------------------------------------------------------------------------
__global__ void __launch_bounds__(256, 1) gemm_kernel(float* __restrict__ out,
                                                      const int* __restrict__ pw,
                                                      const float* __restrict__ scale) {
    extern __shared__ char smem[];
    const int tid = threadIdx.x;
    const int lane = tid & 31;
    const int warp = tid >> 5;
    const int wm = warp & 1;           // 2 warps in M (64 rows each)
    const int wn = warp >> 1;          // 4 warps in N (64 cols each)
    const int bn0 = blockIdx.x * BN;
    const int bm0 = blockIdx.y * BM;

    float acc[4][8][4];
#pragma unroll
    for (int i = 0; i < 4; i++)
#pragma unroll
        for (int j = 0; j < 8; j++)
#pragma unroll
            for (int k = 0; k < 4; k++) acc[i][j][k] = 0.0f;

    // prologue: stages 0,1
#pragma unroll
    for (int s = 0; s < STAGES - 1; s++) {
        load_stage(smem, s, s, bm0, bn0, tid, pw);
        CP_COMMIT();
    }
    CP_WAIT(1);
    __syncthreads();

    int slot = 0;
    for (int kt = 0; kt < KT; kt++) {
        // issue next stage (slot reuse is safe: guarded by the trailing sync)
        int nk = kt + STAGES - 1;
        if (nk < KT) {
            int ns = slot + (STAGES - 1);
            if (ns >= STAGES) ns -= STAGES;
            load_stage(smem, ns, nk, bm0, bn0, tid, pw);
        }
        CP_COMMIT();

        char* stg = smem + slot * STG_B;
        uint32_t sA = (uint32_t)__cvta_generic_to_shared(stg);
        uint32_t sB = (uint32_t)__cvta_generic_to_shared(stg + A_STG_B);

#pragma unroll
        for (int kk = 0; kk < BK; kk += 16) {
            uint32_t a[4][4];
#pragma unroll
            for (int am = 0; am < 4; am++) {
                int row = wm * 64 + am * 16 + (lane & 15);
                int k = kk + ((lane >> 4) << 3);
                ldsm_x4(a[am], sA + (uint32_t)(row * LDSH + k) * 2);
            }
#pragma unroll
            for (int p = 0; p < 4; p++) {
                uint32_t b[4];
                int sel = lane >> 3;
                int n = wn * 64 + p * 16 + (lane & 7) + ((sel >> 1) << 3);
                int k = kk + ((sel & 1) << 3);
                ldsm_x4(b, sB + (uint32_t)(n * LDSH + k) * 2);
#pragma unroll
                for (int am = 0; am < 4; am++) {
                    mma16816(acc[am][2 * p],     a[am], b[0], b[1]);
                    mma16816(acc[am][2 * p + 1], a[am], b[2], b[3]);
                }
            }
        }

        CP_WAIT(1);
        __syncthreads();
        if (++slot == STAGES) slot = 0;
    }

    // epilogue
    const float s = __ldg(scale);
#pragma unroll
    for (int am = 0; am < 4; am++) {
#pragma unroll
        for (int bn = 0; bn < 8; bn++) {
            int row0 = bm0 + wm * 64 + am * 16 + (lane >> 2);
            int col = bn0 + wn * 64 + bn * 8 + ((lane & 3) << 1);
            float2 v0 = make_float2(acc[am][bn][0] * s, acc[am][bn][1] * s);
            float2 v1 = make_float2(acc[am][bn][2] * s, acc[am][bn][3] * s);
            *reinterpret_cast<float2*>(out + (size_t)row0 * NF + col) = v0;
            *reinterpret_cast<float2*>(out + (size_t)(row0 + 8) * NF + col) = v1;
        }
    }
}

// ---------------------------------------------------------------------------
extern "C" void kernel_launch(void* const* d_in, const int* in_sizes, int n_in,
                              void* d_out, int out_size) {
    const float* x     = (const float*)d_in[0];
    const int*   pw    = (const int*)d_in[1];
    const float* scale = (const float*)d_in[2];
    float*       out   = (float*)d_out;

    {   // x -> fp16
        size_t chunks = (size_t)TOKENS * KF / 8;
        convert_x_kernel<<<(unsigned)(chunks / 256), 256>>>(x);
    }
    {   // fused-decode GEMM
        cudaFuncSetAttribute(gemm_kernel, cudaFuncAttributeMaxDynamicSharedMemorySize,
                             SMEM_TOTAL);
        dim3 grid(NF / BN, TOKENS / BM);    // 16 x 64
        gemm_kernel<<<grid, 256, SMEM_TOTAL>>>(out, pw, scale);
    }
}

// round 12
// speedup vs baseline: 1.2157x; 1.2157x over previous
#include <cuda_runtime.h>
#include <cuda_fp16.h>
#include <cstdint>

// ============================================================================
// PackedBitLinear: out = x @ W^T * scale   (abs-max row scaling cancels).
// tcgen05 rejected by harness PTX target (sm_103 w/o 'a') -> HMMA mma.sync.
// R12: warp-specialized GEMM. 384 threads:
//   warps 0-7 : pure consumers, 64x64 warp tile, LDSM + mma.sync only
//   warps 8-11: producers - A tile cp.async + 2-bit W decode -> fp16 smem
// mbarrier full/empty ring (3 stages), no __syncthreads in mainloop.
// ============================================================================

#define TOKENS 8192
#define NF 4096
#define KF 4096
#define PACKED_IN 256

#define BM 128
#define BN 256
#define BK 64                     // halves of K per stage
#define KT (KF / BK)              // 64
#define STAGES 3
#define LDSH 72                   // row stride in halves
#define ROWB (LDSH * 2)           // 144 B row stride (LDSM conflict-free)
#define A_STG_B (BM * ROWB)       // 18432
#define B_STG_B (BN * ROWB)       // 36864
#define STG_B (A_STG_B + B_STG_B) // 55296
#define SM_TILE 1024
#define SMEM_TOTAL (SM_TILE + STAGES * STG_B)   // 166912

static __device__ __half g_XH[(size_t)TOKENS * KF];   // 64 MB fp16 activations

// ---------------------------------------------------------------------------
__device__ __forceinline__ uint32_t smem_u32(const void* p) {
    uint32_t a;
    asm("{ .reg .u64 t; cvta.to.shared.u64 t, %1; cvt.u32.u64 %0, t; }" : "=r"(a) : "l"(p));
    return a;
}
#define MBAR_INIT(a, n) \
    asm volatile("mbarrier.init.shared.b64 [%0], %1;" :: "r"(a), "r"((uint32_t)(n)) : "memory")
#define MBAR_ARRIVE(a) \
    asm volatile("mbarrier.arrive.release.cta.shared::cta.b64 _, [%0];" :: "r"(a) : "memory")

__device__ __forceinline__ void mbar_wait(uint32_t addr, uint32_t parity) {
    uint32_t done;
    asm volatile(
        "{ .reg .pred p; mbarrier.try_wait.parity.acquire.cta.shared::cta.b64 p, [%1], %2;"
        " selp.b32 %0,1,0,p; }" : "=r"(done) : "r"(addr), "r"(parity) : "memory");
    if (!done) {
        asm volatile(
            "{ .reg .pred P1;\n"
            "W_%=: mbarrier.try_wait.parity.acquire.cta.shared::cta.b64 P1, [%0], %1, 0x989680;\n"
            "@P1 bra.uni D_%=; bra.uni W_%=; D_%=: }\n"
            :: "r"(addr), "r"(parity) : "memory");
    }
}
#define CPA16(dst, src) \
    asm volatile("cp.async.cg.shared.global [%0], [%1], 16;\n" :: "r"(dst), "l"(src))
#define CPA_MBAR(b) \
    asm volatile("cp.async.mbarrier.arrive.noinc.shared::cta.b64 [%0];" :: "r"(b) : "memory")
#define STS128(a, r0, r1, r2, r3) \
    asm volatile("st.shared.v4.b32 [%0], {%1,%2,%3,%4};" \
                 :: "r"(a), "r"(r0), "r"(r1), "r"(r2), "r"(r3) : "memory")

__device__ __forceinline__ void ldsm_x4(uint32_t (&r)[4], uint32_t addr) {
    asm volatile("ldmatrix.sync.aligned.m8n8.x4.shared.b16 {%0,%1,%2,%3}, [%4];\n"
                 : "=r"(r[0]), "=r"(r[1]), "=r"(r[2]), "=r"(r[3]) : "r"(addr));
}
__device__ __forceinline__ void mma16816(float (&c)[4], const uint32_t (&a)[4],
                                         uint32_t b0, uint32_t b1) {
    asm volatile(
        "mma.sync.aligned.m16n8k16.row.col.f32.f16.f16.f32 "
        "{%0,%1,%2,%3},{%4,%5,%6,%7},{%8,%9},{%0,%1,%2,%3};\n"
        : "+f"(c[0]), "+f"(c[1]), "+f"(c[2]), "+f"(c[3])
        : "r"(a[0]), "r"(a[1]), "r"(a[2]), "r"(a[3]), "r"(b0), "r"(b1));
}

// decode one int32 (16 ternary {0,1,2}) -> 16 exact fp16 {-1,0,1} -> 32B smem
// half bits 0x6400|v == 1024+v exactly; hsub2 with 1025 -> v-1, exact.
__device__ __forceinline__ void dec32(uint32_t addr, int v) {
    const uint32_t c1025 = 0x64016401u;
    uint32_t r[8];
#pragma unroll
    for (int j = 0; j < 8; j++) {
        uint32_t lo = ((uint32_t)v >> (4 * j)) & 3u;
        uint32_t hi = ((uint32_t)v >> (4 * j + 2)) & 3u;
        uint32_t pk = 0x64006400u | lo | (hi << 16);
        __half2 h = __hsub2(*reinterpret_cast<__half2*>(&pk),
                            *reinterpret_cast<const __half2*>(&c1025));
        r[j] = *reinterpret_cast<uint32_t*>(&h);
    }
    STS128(addr,      r[0], r[1], r[2], r[3]);
    STS128(addr + 16, r[4], r[5], r[6], r[7]);
}

// ---------------------------------------------------------------------------
__global__ void __launch_bounds__(256) convert_x_kernel(const float* __restrict__ x) {
    size_t i = (size_t)blockIdx.x * blockDim.x + threadIdx.x;
    const float4* p = reinterpret_cast<const float4*>(x) + 2 * i;
    float4 a = p[0], b = p[1];
    __half2 h0 = __floats2half2_rn(a.x, a.y), h1 = __floats2half2_rn(a.z, a.w);
    __half2 h2 = __floats2half2_rn(b.x, b.y), h3 = __floats2half2_rn(b.z, b.w);
    uint4 u;
    u.x = *reinterpret_cast<uint32_t*>(&h0); u.y = *reinterpret_cast<uint32_t*>(&h1);
    u.z = *reinterpret_cast<uint32_t*>(&h2); u.w = *reinterpret_cast<uint32_t*>(&h3);
    reinterpret_cast<uint4*>(g_XH)[i] = u;
}

// ---------------------------------------------------------------------------
__global__ void __launch_bounds__(384, 1) gemm_kernel(float* __restrict__ out,
                                                      const int* __restrict__ pw,
                                                      const float* __restrict__ scale) {
    extern __shared__ char smem[];
    const uint32_t sb = smem_u32(smem);
    const int tid = threadIdx.x, wid = tid >> 5, lane = tid & 31;
    const int bn0 = blockIdx.x * BN, bm0 = blockIdx.y * BM;

    if (tid == 0) {
#pragma unroll
        for (int s = 0; s < STAGES; s++) {
            MBAR_INIT(sb + s * 8, 256);        // full: 128 decode + 128 cp arrivals
            MBAR_INIT(sb + 32 + s * 8, 8);     // empty: 8 consumer warps
        }
    }
    __syncthreads();

    if (wid >= 8) {
        // ================= producers (128 threads) =================
        const int pt = tid - 256;
        const int4* gb0 = reinterpret_cast<const int4*>(pw + (size_t)(bn0 + pt) * PACKED_IN);
        const int4* gb1 = reinterpret_cast<const int4*>(pw + (size_t)(bn0 + pt + 128) * PACKED_IN);
        const __half* gA = g_XH + (size_t)bm0 * KF;
        int4 c0 = __ldg(gb0), c1 = __ldg(gb1);      // prefetch kt=0
        int slot = 0; uint32_t ph = 1;              // empty barriers start "ready"
        for (int kt = 0; kt < KT; kt++) {
            mbar_wait(sb + 32 + slot * 8, ph);
            const uint32_t sA = sb + SM_TILE + slot * STG_B;
            const __half* gk = gA + (size_t)kt * BK;
#pragma unroll
            for (int i = 0; i < 8; i++) {            // A: 1024 16B chunks / 128 thr
                int c = pt + i * 128;
                int row = c >> 3, ci = c & 7;
                CPA16(sA + (uint32_t)row * ROWB + ci * 16,
                      gk + (size_t)row * KF + ci * 8);
            }
            int nk = (kt + 1 < KT) ? kt + 1 : kt;    // prefetch next packed W
            int4 n0 = __ldg(gb0 + nk), n1 = __ldg(gb1 + nk);
            const uint32_t rb0 = sA + A_STG_B + (uint32_t)pt * ROWB;       // row pt
            const uint32_t rb1 = rb0 + 128u * ROWB;                        // row pt+128
            dec32(rb0,      c0.x); dec32(rb0 + 32, c0.y);
            dec32(rb0 + 64, c0.z); dec32(rb0 + 96, c0.w);
            dec32(rb1,      c1.x); dec32(rb1 + 32, c1.y);
            dec32(rb1 + 64, c1.z); dec32(rb1 + 96, c1.w);
            c0 = n0; c1 = n1;
            CPA_MBAR(sb + slot * 8);                 // A completion arrive
            MBAR_ARRIVE(sb + slot * 8);              // decode (release) arrive
            if (++slot == STAGES) { slot = 0; ph ^= 1; }
        }
    } else {
        // ================= consumers (8 warps, 64x64 tiles) =================
        const int wm = wid & 1, wn = wid >> 1;
        float acc[4][8][4];
#pragma unroll
        for (int i = 0; i < 4; i++)
#pragma unroll
            for (int j = 0; j < 8; j++)
#pragma unroll
                for (int k = 0; k < 4; k++) acc[i][j][k] = 0.0f;

        int slot = 0; uint32_t ph = 0;
        for (int kt = 0; kt < KT; kt++) {
            mbar_wait(sb + slot * 8, ph);
            const uint32_t sA = sb + SM_TILE + slot * STG_B;
            const uint32_t sB = sA + A_STG_B;
#pragma unroll
            for (int kk = 0; kk < BK; kk += 16) {
                uint32_t a[4][4];
#pragma unroll
                for (int am = 0; am < 4; am++) {
                    int row = wm * 64 + am * 16 + (lane & 15);
                    int k = kk + ((lane >> 4) << 3);
                    ldsm_x4(a[am], sA + (uint32_t)row * ROWB + k * 2);
                }
#pragma unroll
                for (int p = 0; p < 4; p++) {
                    uint32_t b[4];
                    int sel = lane >> 3;
                    int n = wn * 64 + p * 16 + (lane & 7) + ((sel >> 1) << 3);
                    int k = kk + ((sel & 1) << 3);
                    ldsm_x4(b, sB + (uint32_t)n * ROWB + k * 2);
#pragma unroll
                    for (int am = 0; am < 4; am++) {
                        mma16816(acc[am][2 * p],     a[am], b[0], b[1]);
                        mma16816(acc[am][2 * p + 1], a[am], b[2], b[3]);
                    }
                }
            }
            if (lane == 0) MBAR_ARRIVE(sb + 32 + slot * 8);
            if (++slot == STAGES) { slot = 0; ph ^= 1; }
        }

        // epilogue
        const float s = __ldg(scale);
#pragma unroll
        for (int am = 0; am < 4; am++) {
#pragma unroll
            for (int bn = 0; bn < 8; bn++) {
                int row0 = bm0 + wm * 64 + am * 16 + (lane >> 2);
                int col = bn0 + wn * 64 + bn * 8 + ((lane & 3) << 1);
                float2 v0 = make_float2(acc[am][bn][0] * s, acc[am][bn][1] * s);
                float2 v1 = make_float2(acc[am][bn][2] * s, acc[am][bn][3] * s);
                *reinterpret_cast<float2*>(out + (size_t)row0 * NF + col) = v0;
                *reinterpret_cast<float2*>(out + (size_t)(row0 + 8) * NF + col) = v1;
            }
        }
    }
}

// ---------------------------------------------------------------------------
extern "C" void kernel_launch(void* const* d_in, const int* in_sizes, int n_in,
                              void* d_out, int out_size) {
    const float* x     = (const float*)d_in[0];
    const int*   pw    = (const int*)d_in[1];
    const float* scale = (const float*)d_in[2];
    float*       out   = (float*)d_out;

    {   // x -> fp16
        size_t chunks = (size_t)TOKENS * KF / 8;
        convert_x_kernel<<<(unsigned)(chunks / 256), 256>>>(x);
    }
    {   // warp-specialized fused-decode GEMM
        cudaFuncSetAttribute(gemm_kernel, cudaFuncAttributeMaxDynamicSharedMemorySize,
                             SMEM_TOTAL);
        dim3 grid(NF / BN, TOKENS / BM);    // 16 x 64 = 1024 CTAs
        gemm_kernel<<<grid, 384, SMEM_TOTAL>>>(out, pw, scale);
    }
}

// round 13
// speedup vs baseline: 1.2565x; 1.0336x over previous
#include <cuda_runtime.h>
#include <cuda_fp16.h>
#include <cstdint>

// ============================================================================
// PackedBitLinear: out = x @ W^T * scale   (abs-max row scaling cancels).
// tcgen05 rejected by harness PTX target (sm_103 w/o 'a') -> HMMA mma.sync.
// R13: issue-port relief. The fused 2-bit decode oversubscribed the SMSP
// issue ports (660 slots per 512-cyc stage window). Pre-decode W -> fp16
// gmem once; GEMM producers become pure cp.async (A+B), consumers unchanged.
//   kernel 1: x fp32 -> fp16 (g_XH)
//   kernel 2: packed 2-bit -> fp16 (g_WH), exact
//   kernel 3: warp-specialized GEMM 128x256x64, 3-stage mbarrier ring
//             warps 0-7 consumers (64x64, LDSM+MMA), warps 8-11 cp.async
// ============================================================================

#define TOKENS 8192
#define NF 4096
#define KF 4096
#define PACKED_IN 256

#define BM 128
#define BN 256
#define BK 64                     // halves of K per stage
#define KT (KF / BK)              // 64
#define STAGES 3
#define LDSH 72                   // row stride in halves
#define ROWB (LDSH * 2)           // 144 B (LDSM conflict-free)
#define A_STG_B (BM * ROWB)       // 18432
#define B_STG_B (BN * ROWB)       // 36864
#define STG_B (A_STG_B + B_STG_B) // 55296
#define SM_TILE 1024
#define SMEM_TOTAL (SM_TILE + STAGES * STG_B)   // 166912

static __device__ __half g_XH[(size_t)TOKENS * KF];   // 64 MB fp16 activations
static __device__ __half g_WH[(size_t)NF * KF];       // 32 MB fp16 weights

// ---------------------------------------------------------------------------
__device__ __forceinline__ uint32_t smem_u32(const void* p) {
    uint32_t a;
    asm("{ .reg .u64 t; cvta.to.shared.u64 t, %1; cvt.u32.u64 %0, t; }" : "=r"(a) : "l"(p));
    return a;
}
#define MBAR_INIT(a, n) \
    asm volatile("mbarrier.init.shared.b64 [%0], %1;" :: "r"(a), "r"((uint32_t)(n)) : "memory")
#define MBAR_ARRIVE(a) \
    asm volatile("mbarrier.arrive.release.cta.shared::cta.b64 _, [%0];" :: "r"(a) : "memory")

__device__ __forceinline__ void mbar_wait(uint32_t addr, uint32_t parity) {
    uint32_t done;
    asm volatile(
        "{ .reg .pred p; mbarrier.try_wait.parity.acquire.cta.shared::cta.b64 p, [%1], %2;"
        " selp.b32 %0,1,0,p; }" : "=r"(done) : "r"(addr), "r"(parity) : "memory");
    if (!done) {
        asm volatile(
            "{ .reg .pred P1;\n"
            "W_%=: mbarrier.try_wait.parity.acquire.cta.shared::cta.b64 P1, [%0], %1, 0x989680;\n"
            "@P1 bra.uni D_%=; bra.uni W_%=; D_%=: }\n"
            :: "r"(addr), "r"(parity) : "memory");
    }
}
#define CPA16(dst, src) \
    asm volatile("cp.async.cg.shared.global [%0], [%1], 16;\n" :: "r"(dst), "l"(src))
#define CPA_MBAR(b) \
    asm volatile("cp.async.mbarrier.arrive.noinc.shared::cta.b64 [%0];" :: "r"(b) : "memory")

__device__ __forceinline__ void ldsm_x4(uint32_t (&r)[4], uint32_t addr) {
    asm volatile("ldmatrix.sync.aligned.m8n8.x4.shared.b16 {%0,%1,%2,%3}, [%4];\n"
                 : "=r"(r[0]), "=r"(r[1]), "=r"(r[2]), "=r"(r[3]) : "r"(addr));
}
__device__ __forceinline__ void mma16816(float (&c)[4], const uint32_t (&a)[4],
                                         uint32_t b0, uint32_t b1) {
    asm volatile(
        "mma.sync.aligned.m16n8k16.row.col.f32.f16.f16.f32 "
        "{%0,%1,%2,%3},{%4,%5,%6,%7},{%8,%9},{%0,%1,%2,%3};\n"
        : "+f"(c[0]), "+f"(c[1]), "+f"(c[2]), "+f"(c[3])
        : "r"(a[0]), "r"(a[1]), "r"(a[2]), "r"(a[3]), "r"(b0), "r"(b1));
}

// ---------------------------------------------------------------------------
// Kernel 1: x fp32 -> fp16
// ---------------------------------------------------------------------------
__global__ void __launch_bounds__(256) convert_x_kernel(const float* __restrict__ x) {
    size_t i = (size_t)blockIdx.x * blockDim.x + threadIdx.x;
    const float4* p = reinterpret_cast<const float4*>(x) + 2 * i;
    float4 a = p[0], b = p[1];
    __half2 h0 = __floats2half2_rn(a.x, a.y), h1 = __floats2half2_rn(a.z, a.w);
    __half2 h2 = __floats2half2_rn(b.x, b.y), h3 = __floats2half2_rn(b.z, b.w);
    uint4 u;
    u.x = *reinterpret_cast<uint32_t*>(&h0); u.y = *reinterpret_cast<uint32_t*>(&h1);
    u.z = *reinterpret_cast<uint32_t*>(&h2); u.w = *reinterpret_cast<uint32_t*>(&h3);
    reinterpret_cast<uint4*>(g_XH)[i] = u;
}

// ---------------------------------------------------------------------------
// Kernel 2: packed int32 -> 16 exact fp16 {-1,0,1}
// half bits 0x6400|v == 1024+v exactly; hsub2 with 1025 -> v-1, exact.
// ---------------------------------------------------------------------------
__global__ void __launch_bounds__(256) decode_w_kernel(const int* __restrict__ pw) {
    size_t i = (size_t)blockIdx.x * blockDim.x + threadIdx.x;   // one int32
    int v = pw[i];
    const uint32_t c1025 = 0x64016401u;
    uint32_t r[8];
#pragma unroll
    for (int j = 0; j < 8; j++) {
        uint32_t lo = ((uint32_t)v >> (4 * j)) & 3u;
        uint32_t hi = ((uint32_t)v >> (4 * j + 2)) & 3u;
        uint32_t pk = 0x64006400u | lo | (hi << 16);
        __half2 h = __hsub2(*reinterpret_cast<__half2*>(&pk),
                            *reinterpret_cast<const __half2*>(&c1025));
        r[j] = *reinterpret_cast<uint32_t*>(&h);
    }
    uint4* dst = reinterpret_cast<uint4*>(g_WH + i * 16);
    dst[0] = make_uint4(r[0], r[1], r[2], r[3]);
    dst[1] = make_uint4(r[4], r[5], r[6], r[7]);
}

// ---------------------------------------------------------------------------
// Kernel 3: warp-specialized GEMM
// ---------------------------------------------------------------------------
__global__ void __launch_bounds__(384, 1) gemm_kernel(float* __restrict__ out,
                                                      const float* __restrict__ scale) {
    extern __shared__ char smem[];
    const uint32_t sb = smem_u32(smem);
    const int tid = threadIdx.x, wid = tid >> 5, lane = tid & 31;
    const int bn0 = blockIdx.x * BN, bm0 = blockIdx.y * BM;

    if (tid == 0) {
#pragma unroll
        for (int s = 0; s < STAGES; s++) {
            MBAR_INIT(sb + s * 8, 128);        // full: 128 producer cp-arrivals
            MBAR_INIT(sb + 32 + s * 8, 8);     // empty: 8 consumer warps
        }
    }
    __syncthreads();

    if (wid >= 8) {
        // ================= producers (128 threads, pure cp.async) ==========
        const int pt = tid - 256;
        const __half* gA = g_XH + (size_t)bm0 * KF;
        const __half* gB = g_WH + (size_t)bn0 * KF;
        int slot = 0; uint32_t ph = 1;         // empty barriers start "ready"
        for (int kt = 0; kt < KT; kt++) {
            mbar_wait(sb + 32 + slot * 8, ph);
            const uint32_t sA = sb + SM_TILE + slot * STG_B;
            const uint32_t sB = sA + A_STG_B;
            const size_t k0 = (size_t)kt * BK;
#pragma unroll
            for (int i = 0; i < 8; i++) {       // A: 1024 16B chunks
                int c = pt + i * 128;
                int row = c >> 3, ci = c & 7;
                CPA16(sA + (uint32_t)row * ROWB + ci * 16,
                      gA + (size_t)row * KF + k0 + ci * 8);
            }
#pragma unroll
            for (int i = 0; i < 16; i++) {      // B: 2048 16B chunks
                int c = pt + i * 128;
                int row = c >> 3, ci = c & 7;
                CPA16(sB + (uint32_t)row * ROWB + ci * 16,
                      gB + (size_t)row * KF + k0 + ci * 8);
            }
            CPA_MBAR(sb + slot * 8);
            if (++slot == STAGES) { slot = 0; ph ^= 1; }
        }
    } else {
        // ================= consumers (8 warps, 64x64 tiles) ================
        const int wm = wid & 1, wn = wid >> 1;
        float acc[4][8][4];
#pragma unroll
        for (int i = 0; i < 4; i++)
#pragma unroll
            for (int j = 0; j < 8; j++)
#pragma unroll
                for (int k = 0; k < 4; k++) acc[i][j][k] = 0.0f;

        int slot = 0; uint32_t ph = 0;
        for (int kt = 0; kt < KT; kt++) {
            mbar_wait(sb + slot * 8, ph);
            const uint32_t sA = sb + SM_TILE + slot * STG_B;
            const uint32_t sB = sA + A_STG_B;
#pragma unroll
            for (int kk = 0; kk < BK; kk += 16) {
                uint32_t a[4][4];
#pragma unroll
                for (int am = 0; am < 4; am++) {
                    int row = wm * 64 + am * 16 + (lane & 15);
                    int k = kk + ((lane >> 4) << 3);
                    ldsm_x4(a[am], sA + (uint32_t)row * ROWB + k * 2);
                }
#pragma unroll
                for (int p = 0; p < 4; p++) {
                    uint32_t b[4];
                    int sel = lane >> 3;
                    int n = wn * 64 + p * 16 + (lane & 7) + ((sel >> 1) << 3);
                    int k = kk + ((sel & 1) << 3);
                    ldsm_x4(b, sB + (uint32_t)n * ROWB + k * 2);
#pragma unroll
                    for (int am = 0; am < 4; am++) {
                        mma16816(acc[am][2 * p],     a[am], b[0], b[1]);
                        mma16816(acc[am][2 * p + 1], a[am], b[2], b[3]);
                    }
                }
            }
            if (lane == 0) MBAR_ARRIVE(sb + 32 + slot * 8);
            if (++slot == STAGES) { slot = 0; ph ^= 1; }
        }

        // epilogue
        const float s = __ldg(scale);
#pragma unroll
        for (int am = 0; am < 4; am++) {
#pragma unroll
            for (int bn = 0; bn < 8; bn++) {
                int row0 = bm0 + wm * 64 + am * 16 + (lane >> 2);
                int col = bn0 + wn * 64 + bn * 8 + ((lane & 3) << 1);
                float2 v0 = make_float2(acc[am][bn][0] * s, acc[am][bn][1] * s);
                float2 v1 = make_float2(acc[am][bn][2] * s, acc[am][bn][3] * s);
                *reinterpret_cast<float2*>(out + (size_t)row0 * NF + col) = v0;
                *reinterpret_cast<float2*>(out + (size_t)(row0 + 8) * NF + col) = v1;
            }
        }
    }
}

// ---------------------------------------------------------------------------
extern "C" void kernel_launch(void* const* d_in, const int* in_sizes, int n_in,
                              void* d_out, int out_size) {
    const float* x     = (const float*)d_in[0];
    const int*   pw    = (const int*)d_in[1];
    const float* scale = (const float*)d_in[2];
    float*       out   = (float*)d_out;

    {   // x -> fp16
        size_t chunks = (size_t)TOKENS * KF / 8;
        convert_x_kernel<<<(unsigned)(chunks / 256), 256>>>(x);
    }
    {   // packed 2-bit -> fp16 weights
        size_t ints = (size_t)NF * KF / 16;
        decode_w_kernel<<<(unsigned)(ints / 256), 256>>>(pw);
    }
    {   // warp-specialized GEMM
        cudaFuncSetAttribute(gemm_kernel, cudaFuncAttributeMaxDynamicSharedMemorySize,
                             SMEM_TOTAL);
        dim3 grid(NF / BN, TOKENS / BM);    // 16 x 64 = 1024 CTAs
        gemm_kernel<<<grid, 384, SMEM_TOTAL>>>(out, scale);
    }
}

// round 14
// speedup vs baseline: 1.3841x; 1.1015x over previous
#include <cuda_runtime.h>
#include <cuda_fp16.h>
#include <cstdint>

// ============================================================================
// PackedBitLinear: out = x @ W^T * scale   (abs-max row scaling cancels).
// tcgen05 rejected by harness PTX target (sm_103 w/o 'a') -> HMMA mma.sync.
// R14: latency relief. 4-stage ring (deeper slack), grouped LDSM prefetch
// per kk (no mid-kk LDS stalls), 2 producer warps (320 thr -> 204 reg cap).
//   kernel 1: x fp32 -> fp16 (g_XH)
//   kernel 2: packed 2-bit -> fp16 (g_WH), exact
//   kernel 3: warp-specialized GEMM 128x256x64, 4-stage mbarrier ring
// ============================================================================

#define TOKENS 8192
#define NF 4096
#define KF 4096

#define BM 128
#define BN 256
#define BK 64                     // halves of K per stage
#define KT (KF / BK)              // 64
#define STAGES 4
#define LDSH 72                   // row stride in halves
#define ROWB (LDSH * 2)           // 144 B (LDSM conflict-free)
#define A_STG_B (BM * ROWB)       // 18432
#define B_STG_B (BN * ROWB)       // 36864
#define STG_B (A_STG_B + B_STG_B) // 55296
#define SM_TILE 1024
#define SMEM_TOTAL (SM_TILE + STAGES * STG_B)   // 222208

#define NTHREADS 320              // 8 consumer warps + 2 producer warps

static __device__ __half g_XH[(size_t)TOKENS * KF];   // 64 MB fp16 activations
static __device__ __half g_WH[(size_t)NF * KF];       // 32 MB fp16 weights

// ---------------------------------------------------------------------------
__device__ __forceinline__ uint32_t smem_u32(const void* p) {
    uint32_t a;
    asm("{ .reg .u64 t; cvta.to.shared.u64 t, %1; cvt.u32.u64 %0, t; }" : "=r"(a) : "l"(p));
    return a;
}
#define MBAR_INIT(a, n) \
    asm volatile("mbarrier.init.shared.b64 [%0], %1;" :: "r"(a), "r"((uint32_t)(n)) : "memory")
#define MBAR_ARRIVE(a) \
    asm volatile("mbarrier.arrive.release.cta.shared::cta.b64 _, [%0];" :: "r"(a) : "memory")

__device__ __forceinline__ void mbar_wait(uint32_t addr, uint32_t parity) {
    uint32_t done;
    asm volatile(
        "{ .reg .pred p; mbarrier.try_wait.parity.acquire.cta.shared::cta.b64 p, [%1], %2;"
        " selp.b32 %0,1,0,p; }" : "=r"(done) : "r"(addr), "r"(parity) : "memory");
    if (!done) {
        asm volatile(
            "{ .reg .pred P1;\n"
            "W_%=: mbarrier.try_wait.parity.acquire.cta.shared::cta.b64 P1, [%0], %1, 0x989680;\n"
            "@P1 bra.uni D_%=; bra.uni W_%=; D_%=: }\n"
            :: "r"(addr), "r"(parity) : "memory");
    }
}
#define CPA16(dst, src) \
    asm volatile("cp.async.cg.shared.global [%0], [%1], 16;\n" :: "r"(dst), "l"(src))
#define CPA_MBAR(b) \
    asm volatile("cp.async.mbarrier.arrive.noinc.shared::cta.b64 [%0];" :: "r"(b) : "memory")

__device__ __forceinline__ void ldsm_x4(uint32_t (&r)[4], uint32_t addr) {
    asm volatile("ldmatrix.sync.aligned.m8n8.x4.shared.b16 {%0,%1,%2,%3}, [%4];\n"
                 : "=r"(r[0]), "=r"(r[1]), "=r"(r[2]), "=r"(r[3]) : "r"(addr));
}
__device__ __forceinline__ void mma16816(float (&c)[4], const uint32_t (&a)[4],
                                         uint32_t b0, uint32_t b1) {
    asm volatile(
        "mma.sync.aligned.m16n8k16.row.col.f32.f16.f16.f32 "
        "{%0,%1,%2,%3},{%4,%5,%6,%7},{%8,%9},{%0,%1,%2,%3};\n"
        : "+f"(c[0]), "+f"(c[1]), "+f"(c[2]), "+f"(c[3])
        : "r"(a[0]), "r"(a[1]), "r"(a[2]), "r"(a[3]), "r"(b0), "r"(b1));
}

// ---------------------------------------------------------------------------
// Kernel 1: x fp32 -> fp16
// ---------------------------------------------------------------------------
__global__ void __launch_bounds__(256) convert_x_kernel(const float* __restrict__ x) {
    size_t i = (size_t)blockIdx.x * blockDim.x + threadIdx.x;
    const float4* p = reinterpret_cast<const float4*>(x) + 2 * i;
    float4 a = p[0], b = p[1];
    __half2 h0 = __floats2half2_rn(a.x, a.y), h1 = __floats2half2_rn(a.z, a.w);
    __half2 h2 = __floats2half2_rn(b.x, b.y), h3 = __floats2half2_rn(b.z, b.w);
    uint4 u;
    u.x = *reinterpret_cast<uint32_t*>(&h0); u.y = *reinterpret_cast<uint32_t*>(&h1);
    u.z = *reinterpret_cast<uint32_t*>(&h2); u.w = *reinterpret_cast<uint32_t*>(&h3);
    reinterpret_cast<uint4*>(g_XH)[i] = u;
}

// ---------------------------------------------------------------------------
// Kernel 2: packed int32 -> 16 exact fp16 {-1,0,1}
// half bits 0x6400|v == 1024+v exactly; hsub2 with 1025 -> v-1, exact.
// ---------------------------------------------------------------------------
__global__ void __launch_bounds__(256) decode_w_kernel(const int* __restrict__ pw) {
    size_t i = (size_t)blockIdx.x * blockDim.x + threadIdx.x;   // one int32
    int v = pw[i];
    const uint32_t c1025 = 0x64016401u;
    uint32_t r[8];
#pragma unroll
    for (int j = 0; j < 8; j++) {
        uint32_t lo = ((uint32_t)v >> (4 * j)) & 3u;
        uint32_t hi = ((uint32_t)v >> (4 * j + 2)) & 3u;
        uint32_t pk = 0x64006400u | lo | (hi << 16);
        __half2 h = __hsub2(*reinterpret_cast<__half2*>(&pk),
                            *reinterpret_cast<const __half2*>(&c1025));
        r[j] = *reinterpret_cast<uint32_t*>(&h);
    }
    uint4* dst = reinterpret_cast<uint4*>(g_WH + i * 16);
    dst[0] = make_uint4(r[0], r[1], r[2], r[3]);
    dst[1] = make_uint4(r[4], r[5], r[6], r[7]);
}

// ---------------------------------------------------------------------------
// Kernel 3: warp-specialized GEMM
// ---------------------------------------------------------------------------
__global__ void __launch_bounds__(NTHREADS, 1) gemm_kernel(float* __restrict__ out,
                                                           const float* __restrict__ scale) {
    extern __shared__ char smem[];
    const uint32_t sb = smem_u32(smem);
    const int tid = threadIdx.x, wid = tid >> 5, lane = tid & 31;
    const int bn0 = blockIdx.x * BN, bm0 = blockIdx.y * BM;

    if (tid == 0) {
#pragma unroll
        for (int s = 0; s < STAGES; s++) {
            MBAR_INIT(sb + s * 8, 64);         // full: 64 producer cp-arrivals
            MBAR_INIT(sb + 64 + s * 8, 8);     // empty: 8 consumer warps
        }
    }
    __syncthreads();

    if (wid >= 8) {
        // ========== producers (64 threads, pure cp.async) ==========
        const int pt = tid - 256;
        const __half* gA = g_XH + (size_t)bm0 * KF;
        const __half* gB = g_WH + (size_t)bn0 * KF;
        int slot = 0; uint32_t ph = 1;          // empty barriers start "ready"
        for (int kt = 0; kt < KT; kt++) {
            mbar_wait(sb + 64 + slot * 8, ph);
            const uint32_t sA = sb + SM_TILE + slot * STG_B;
            const uint32_t sB = sA + A_STG_B;
            const size_t k0 = (size_t)kt * BK;
#pragma unroll
            for (int i = 0; i < 16; i++) {      // A: 1024 16B chunks / 64 thr
                int c = pt + i * 64;
                int row = c >> 3, ci = c & 7;
                CPA16(sA + (uint32_t)row * ROWB + ci * 16,
                      gA + (size_t)row * KF + k0 + ci * 8);
            }
#pragma unroll
            for (int i = 0; i < 32; i++) {      // B: 2048 16B chunks / 64 thr
                int c = pt + i * 64;
                int row = c >> 3, ci = c & 7;
                CPA16(sB + (uint32_t)row * ROWB + ci * 16,
                      gB + (size_t)row * KF + k0 + ci * 8);
            }
            CPA_MBAR(sb + slot * 8);
            if (++slot == STAGES) { slot = 0; ph ^= 1; }
        }
    } else {
        // ========== consumers (8 warps, 64x64 tiles) ==========
        const int wm = wid & 1, wn = wid >> 1;
        float acc[4][8][4];
#pragma unroll
        for (int i = 0; i < 4; i++)
#pragma unroll
            for (int j = 0; j < 8; j++)
#pragma unroll
                for (int k = 0; k < 4; k++) acc[i][j][k] = 0.0f;

        // per-warp LDSM base offsets (lane-dependent parts precomputed)
        const uint32_t aoff = (uint32_t)(wm * 64 + (lane & 15)) * ROWB
                            + (uint32_t)((lane >> 4) << 3) * 2;
        const int selb = lane >> 3;
        const uint32_t boff = (uint32_t)(wn * 64 + (lane & 7) + ((selb >> 1) << 3)) * ROWB
                            + (uint32_t)((selb & 1) << 3) * 2;

        int slot = 0; uint32_t ph = 0;
        for (int kt = 0; kt < KT; kt++) {
            mbar_wait(sb + slot * 8, ph);
            const uint32_t sA = sb + SM_TILE + slot * STG_B + aoff;
            const uint32_t sB = sb + SM_TILE + slot * STG_B + A_STG_B + boff;
#pragma unroll
            for (int kk = 0; kk < BK; kk += 16) {
                // group-prefetch: all 8 LDSMs before any MMA
                uint32_t a[4][4], b[4][4];
#pragma unroll
                for (int am = 0; am < 4; am++)
                    ldsm_x4(a[am], sA + (uint32_t)(am * 16) * ROWB + kk * 2);
#pragma unroll
                for (int p = 0; p < 4; p++)
                    ldsm_x4(b[p], sB + (uint32_t)(p * 16) * ROWB + kk * 2);
#pragma unroll
                for (int p = 0; p < 4; p++)
#pragma unroll
                    for (int am = 0; am < 4; am++) {
                        mma16816(acc[am][2 * p],     a[am], b[p][0], b[p][1]);
                        mma16816(acc[am][2 * p + 1], a[am], b[p][2], b[p][3]);
                    }
            }
            if (lane == 0) MBAR_ARRIVE(sb + 64 + slot * 8);
            if (++slot == STAGES) { slot = 0; ph ^= 1; }
        }

        // epilogue
        const float s = __ldg(scale);
#pragma unroll
        for (int am = 0; am < 4; am++) {
#pragma unroll
            for (int bn = 0; bn < 8; bn++) {
                int row0 = bm0 + wm * 64 + am * 16 + (lane >> 2);
                int col = bn0 + wn * 64 + bn * 8 + ((lane & 3) << 1);
                float2 v0 = make_float2(acc[am][bn][0] * s, acc[am][bn][1] * s);
                float2 v1 = make_float2(acc[am][bn][2] * s, acc[am][bn][3] * s);
                *reinterpret_cast<float2*>(out + (size_t)row0 * NF + col) = v0;
                *reinterpret_cast<float2*>(out + (size_t)(row0 + 8) * NF + col) = v1;
            }
        }
    }
}

// ---------------------------------------------------------------------------
extern "C" void kernel_launch(void* const* d_in, const int* in_sizes, int n_in,
                              void* d_out, int out_size) {
    const float* x     = (const float*)d_in[0];
    const int*   pw    = (const int*)d_in[1];
    const float* scale = (const float*)d_in[2];
    float*       out   = (float*)d_out;

    {   // x -> fp16
        size_t chunks = (size_t)TOKENS * KF / 8;
        convert_x_kernel<<<(unsigned)(chunks / 256), 256>>>(x);
    }
    {   // packed 2-bit -> fp16 weights
        size_t ints = (size_t)NF * KF / 16;
        decode_w_kernel<<<(unsigned)(ints / 256), 256>>>(pw);
    }
    {   // warp-specialized GEMM
        cudaFuncSetAttribute(gemm_kernel, cudaFuncAttributeMaxDynamicSharedMemorySize,
                             SMEM_TOTAL);
        dim3 grid(NF / BN, TOKENS / BM);    // 16 x 64 = 1024 CTAs
        gemm_kernel<<<grid, NTHREADS, SMEM_TOTAL>>>(out, scale);
    }
}